// round 14
// baseline (speedup 1.0000x reference)
#include <cuda_runtime.h>
#include <cuda_bf16.h>
#include <cstdint>

// Problem constants
#define NB   32      // batch
#define NC   8192    // checks
#define NV   16384   // vars
#define NITR 15
#define RCAP 64      // check degree slots (tiers of 16); RCAP=64 -> slot>>6 = check id
#define CCAP 40      // var degree slots (tiers of 8)

#define EDGE_SLOTS (NC * RCAP + 1)   // +1 dummy slot for padded var edges

// Scratch (allocation-free: __device__ globals)
__device__ int   g_csr_cnt[NC];             // check degrees (padded tiers)
__device__ int   g_csc_row[NV * CCAP];      // SLOT ids (c*RCAP+p); dummy = NC*RCAP
__device__ int   g_csc_cnt[NV];             // var degrees (padded tiers)
__device__ float g_edge[EDGE_SLOTS * NB];   // edge-value buffer: slot-major, batch minor
__device__ float g_vbel[NV * NB];           // beliefs (v, b)
__device__ float g_cmsg[(NC + 1) * NB];     // check msgs; row NC = zeros (dummy gather)
__device__ float g_llr_t[NV * NB];          // channel llrs, transposed
__device__ float g_ssign[NC * NB];          // 1 - 2*syndrome, transposed

// ---------------------------------------------------------------------------
__global__ void zero_cnt_kernel() {
    int tid = blockIdx.x * blockDim.x + threadIdx.x;
    if (tid < NC) g_csr_cnt[tid] = 0;
    if (tid < NV) g_csc_cnt[tid] = 0;
    if (tid < NB) g_cmsg[NC * NB + tid] = 0.0f;   // dummy check row
}

// One warp per H row, 4 uint4 in flight (proven sweet spot).
// CSC records the edge SLOT (c*RCAP + p) — both gather row (slot>>6) and
// scatter address (slot<<5) derive from it.
__global__ void extract_kernel(const uint4* __restrict__ H) {
    int warp = (blockIdx.x * blockDim.x + threadIdx.x) >> 5;
    if (warp >= NC) return;
    int lane = threadIdx.x & 31;
    const uint4* row = H + (size_t)warp * (NV / 4);

    for (int base = lane; base < NV / 4; base += 128) {
        uint4 u0 = row[base];
        uint4 u1 = row[base + 32];
        uint4 u2 = row[base + 64];
        uint4 u3 = row[base + 96];
        #pragma unroll
        for (int g = 0; g < 4; g++) {
            uint4 u = (g == 0) ? u0 : (g == 1) ? u1 : (g == 2) ? u2 : u3;
            if (u.x | u.y | u.z | u.w) {
                int vb = (base + g * 32) * 4;
                #pragma unroll
                for (int j = 0; j < 4; j++) {
                    unsigned val = (j == 0) ? u.x : (j == 1) ? u.y : (j == 2) ? u.z : u.w;
                    if (val) {
                        int v = vb + j;
                        int p = atomicAdd(&g_csr_cnt[warp], 1);
                        if (p < RCAP) {
                            int q = atomicAdd(&g_csc_cnt[v], 1);
                            if (q < CCAP) g_csc_row[v * CCAP + q] = warp * RCAP + p;
                        }
                    }
                }
            }
        }
    }
}

// Merged pad + prep (R10 structure).
// Pad: tier degrees; zero check pad slots in g_edge; dummy-slot-fill var pads.
#define PADB 64
__global__ void padprep_kernel(const float* __restrict__ syndrome,
                               const float* __restrict__ llr) {
    __shared__ float tile[32][33];
    int bid = blockIdx.x;
    if (bid < PADB) {
        int tid = bid * 256 + threadIdx.x;
        if (tid < NC) {
            int cnt = g_csr_cnt[tid]; if (cnt > RCAP) cnt = RCAP;
            int p = (cnt + 15) & ~15; if (p > RCAP) p = RCAP;
            if (p == 0) p = 16;
            for (int k = cnt; k < p; k++) {
                float* s = &g_edge[(size_t)(tid * RCAP + k) * NB];
                #pragma unroll
                for (int b = 0; b < NB; b++) s[b] = 0.0f;
            }
            g_csr_cnt[tid] = p;
        }
        if (tid < NV) {
            int cnt = g_csc_cnt[tid]; if (cnt > CCAP) cnt = CCAP;
            int p = (cnt + 7) & ~7;   if (p > CCAP) p = CCAP;
            if (p == 0) p = 8;
            for (int k = cnt; k < p; k++) g_csc_row[tid * CCAP + k] = NC * RCAP;
            g_csc_cnt[tid] = p;
        }
        return;
    }
    int tx = threadIdx.x & 31, ty = threadIdx.x >> 5;
    int t = bid - PADB;
    if (t < NV / 32) {
        int v0 = t * 32;
        #pragma unroll
        for (int i = 0; i < 32; i += 8)
            tile[ty + i][tx] = llr[(size_t)(ty + i) * NV + v0 + tx];
        __syncthreads();
        #pragma unroll
        for (int i = 0; i < 32; i += 8) {
            float x = tile[tx][ty + i];
            int idx = (v0 + ty + i) * NB + tx;
            g_llr_t[idx] = x;
            g_vbel[idx]  = x;
        }
    } else {
        int c0 = (t - NV / 32) * 32;
        #pragma unroll
        for (int i = 0; i < 32; i += 8)
            tile[ty + i][tx] = syndrome[(size_t)(ty + i) * NC + c0 + tx];
        __syncthreads();
        #pragma unroll
        for (int i = 0; i < 32; i += 8)
            g_ssign[(c0 + ty + i) * NB + tx] = 1.0f - 2.0f * tile[tx][ty + i];
    }
}

__device__ __forceinline__ float fast_tanh(float x) {
    float y;
    asm("tanh.approx.f32 %0, %1;" : "=f"(y) : "f"(x));
    return y;
}

// Sum N contiguous edge slots (stride NB floats) — addresses are pure
// arithmetic, zero index loads, fully parallel.
template <int N>
__device__ __forceinline__ float edge_sum(const float* __restrict__ eb) {
    float x[N];
    #pragma unroll
    for (int i = 0; i < N; i++) x[i] = eb[i * NB];
    float s = 0.0f;
    #pragma unroll
    for (int i = 0; i < N; i++) s += x[i];
    return s;
}

// Gather 8 cmsg values from a slot pack; slots stay in regs for the scatter.
__device__ __forceinline__ float slot_gather8(int4 a, int4 b, int lane) {
    float x0 = g_cmsg[((a.x >> 6) << 5) + lane];
    float x1 = g_cmsg[((a.y >> 6) << 5) + lane];
    float x2 = g_cmsg[((a.z >> 6) << 5) + lane];
    float x3 = g_cmsg[((a.w >> 6) << 5) + lane];
    float x4 = g_cmsg[((b.x >> 6) << 5) + lane];
    float x5 = g_cmsg[((b.y >> 6) << 5) + lane];
    float x6 = g_cmsg[((b.z >> 6) << 5) + lane];
    float x7 = g_cmsg[((b.w >> 6) << 5) + lane];
    return ((x0 + x1) + (x2 + x3)) + ((x4 + x5) + (x6 + x7));
}

__device__ __forceinline__ void slot_scatter8(int4 a, int4 b, float v, int lane) {
    g_edge[(a.x << 5) + lane] = v;
    g_edge[(a.y << 5) + lane] = v;
    g_edge[(a.z << 5) + lane] = v;
    g_edge[(a.w << 5) + lane] = v;
    g_edge[(b.x << 5) + lane] = v;
    g_edge[(b.y << 5) + lane] = v;
    g_edge[(b.z << 5) + lane] = v;
    g_edge[(b.w << 5) + lane] = v;
}

// Initial scatter: vbel(=llr) into edge slots. Two vars per warp.
__global__ void __launch_bounds__(256, 8)
scatter_init_kernel() {
    int gw = (blockIdx.x * blockDim.x + threadIdx.x) >> 5;
    int lane = threadIdx.x & 31;
    int v0 = gw * 2;
    if (v0 >= NV) return;
    #pragma unroll
    for (int s = 0; s < 2; s++) {
        int v = v0 + s;
        float x = g_llr_t[v * NB + lane];
        int degp = g_csc_cnt[v];
        const int4* p = (const int4*)&g_csc_row[v * CCAP];
        for (int k = 0; k < degp; k += 8) {
            int4 a = p[k >> 2], b = p[(k >> 2) + 1];
            slot_scatter8(a, b, x, lane);
        }
    }
}

// ---------------------------------------------------------------------------
// v -> c : ONE check per warp. Contiguous edge-slot reads — single exposed
// L2 round trip, no index loads at all.
__global__ void __launch_bounds__(256, 8)
check_kernel(const float* __restrict__ w_vc) {
    cudaTriggerProgrammaticLaunchCompletion();
    int c = (blockIdx.x * blockDim.x + threadIdx.x) >> 5;
    int lane = threadIdx.x & 31;
    if (c >= NC) { cudaGridDependencySynchronize(); return; }

    int degp = g_csr_cnt[c];                       // prelude: degree only
    const float* eb = &g_edge[(size_t)c * RCAP * NB + lane];

    cudaGridDependencySynchronize();               // wait: var scatters done

    float sum;
    if (degp == 16)      sum = edge_sum<16>(eb);
    else if (degp == 32) sum = edge_sum<16>(eb) + edge_sum<16>(eb + 16 * NB);
    else {                                          // rare tail (48/64)
        sum = 0.0f;
        for (int k = 0; k < degp; k += 16) sum += edge_sum<16>(eb + k * NB);
    }

    float tt = fast_tanh(0.5f * (*w_vc) * sum);
    g_cmsg[c * NB + lane] = g_ssign[c * NB + lane] * tt;
}

// c -> v : TWO vars per warp. Gather cmsg via slot>>6, damped update,
// scatter v_new back into edge slots.
__global__ void __launch_bounds__(256, 8)
var_kernel(const float* __restrict__ w_cv,
           const float* __restrict__ damping) {
    cudaTriggerProgrammaticLaunchCompletion();
    int gw = (blockIdx.x * blockDim.x + threadIdx.x) >> 5;
    int lane = threadIdx.x & 31;
    int v0 = gw * 2;
    if (v0 >= NV) { cudaGridDependencySynchronize(); return; }
    int v1 = v0 + 1;

    int deg0 = g_csc_cnt[v0];
    int deg1 = g_csc_cnt[v1];
    const int4* p0 = (const int4*)&g_csc_row[v0 * CCAP];
    const int4* p1 = (const int4*)&g_csc_row[v1 * CCAP];

    cudaGridDependencySynchronize();               // wait: check phase done

    float dmp = *damping;
    float wc  = *w_cv;

    // chain 0
    {
        float sum;
        if (deg0 == 8) {
            int4 a = p0[0], b = p0[1];
            sum = slot_gather8(a, b, lane);
            int idx = v0 * NB + lane;
            float vn = dmp * g_vbel[idx] + (1.0f - dmp) * (g_llr_t[idx] + wc * sum);
            g_vbel[idx] = vn;
            slot_scatter8(a, b, vn, lane);
        } else {
            sum = 0.0f;
            for (int k = 0; k < deg0; k += 8)
                sum += slot_gather8(p0[k >> 2], p0[(k >> 2) + 1], lane);
            int idx = v0 * NB + lane;
            float vn = dmp * g_vbel[idx] + (1.0f - dmp) * (g_llr_t[idx] + wc * sum);
            g_vbel[idx] = vn;
            for (int k = 0; k < deg0; k += 8)
                slot_scatter8(p0[k >> 2], p0[(k >> 2) + 1], vn, lane);
        }
    }
    // chain 1
    {
        float sum;
        if (deg1 == 8) {
            int4 a = p1[0], b = p1[1];
            sum = slot_gather8(a, b, lane);
            int idx = v1 * NB + lane;
            float vn = dmp * g_vbel[idx] + (1.0f - dmp) * (g_llr_t[idx] + wc * sum);
            g_vbel[idx] = vn;
            slot_scatter8(a, b, vn, lane);
        } else {
            sum = 0.0f;
            for (int k = 0; k < deg1; k += 8)
                sum += slot_gather8(p1[k >> 2], p1[(k >> 2) + 1], lane);
            int idx = v1 * NB + lane;
            float vn = dmp * g_vbel[idx] + (1.0f - dmp) * (g_llr_t[idx] + wc * sum);
            g_vbel[idx] = vn;
            for (int k = 0; k < deg1; k += 8)
                slot_scatter8(p1[k >> 2], p1[(k >> 2) + 1], vn, lane);
        }
    }
}

// out[b][v] = sigmoid(-belief); smem-tile transpose, coalesced both sides.
__global__ void output_kernel(float* __restrict__ out) {
    __shared__ float tile[32][33];
    cudaGridDependencySynchronize();
    int tx = threadIdx.x & 31, ty = threadIdx.x >> 5;
    int v0 = blockIdx.x * 32;
    #pragma unroll
    for (int i = 0; i < 32; i += 8)
        tile[ty + i][tx] = g_vbel[(v0 + ty + i) * NB + tx];
    __syncthreads();
    #pragma unroll
    for (int i = 0; i < 32; i += 8) {
        float x = tile[tx][ty + i];
        out[(size_t)(ty + i) * NV + v0 + tx] = 1.0f / (1.0f + expf(x));
    }
}

// ---------------------------------------------------------------------------
template <typename... Args>
static void launch_pdl(void (*kern)(Args...), int grid, int block, Args... args) {
    cudaLaunchConfig_t cfg = {};
    cfg.gridDim  = dim3(grid, 1, 1);
    cfg.blockDim = dim3(block, 1, 1);
    cfg.stream   = 0;
    cudaLaunchAttribute attr[1];
    attr[0].id = cudaLaunchAttributeProgrammaticStreamSerialization;
    attr[0].val.programmaticStreamSerializationAllowed = 1;
    cfg.attrs = attr;
    cfg.numAttrs = 1;
    cudaLaunchKernelEx(&cfg, kern, args...);
}

extern "C" void kernel_launch(void* const* d_in, const int* in_sizes, int n_in,
                              void* d_out, int out_size) {
    const float* syndrome = (const float*)d_in[0];   // (32, 8192)
    const uint4* parity   = (const uint4*)d_in[1];   // (8192, 16384) fp32 as bits
    const float* llr      = (const float*)d_in[2];   // (32, 16384)
    const float* w_vc     = (const float*)d_in[3];
    const float* w_cv     = (const float*)d_in[4];
    const float* damping  = (const float*)d_in[5];
    float* out = (float*)d_out;

    zero_cnt_kernel<<<(NV + 255) / 256, 256>>>();
    extract_kernel<<<(NC * 32 + 255) / 256, 256>>>(parity);
    padprep_kernel<<<PADB + NV / 32 + NC / 32, 256>>>(syndrome, llr);
    scatter_init_kernel<<<(NV * 16 + 255) / 256, 256>>>();

    for (int it = 0; it < NITR; it++) {
        launch_pdl(check_kernel, (NC * 32 + 255) / 256, 256, w_vc);
        launch_pdl(var_kernel,   (NV * 16 + 255) / 256, 256, w_cv, damping);
    }

    launch_pdl(output_kernel, NV / 32, 256, out);
}

// round 15
// speedup vs baseline: 2.7609x; 2.7609x over previous
#include <cuda_runtime.h>
#include <cuda_bf16.h>
#include <cstdint>

// Problem constants
#define NB   32      // batch
#define NC   8192    // checks
#define NV   16384   // vars
#define NITR 15
#define RCAP 64      // max check degree slots (mean ~16.4), tiers of 16
#define CCAP 40      // max var degree slots (mean ~8.2), tiers of 8

// Scratch (allocation-free: __device__ globals)
// Adjacency lists store PRE-SCALED indices (idx * NB). Dummy = zero row.
__device__ int   g_csr_col[NC * RCAP];
__device__ int   g_csr_cnt[NC];
__device__ int   g_csc_row[NV * CCAP];
__device__ int   g_csc_cnt[NV];
__device__ float g_vbel[(NV + 1) * NB];   // beliefs (v, b); row NV = zeros
__device__ float g_cmsg[(NC + 1) * NB];   // check msgs (c, b); row NC = zeros
__device__ float g_llr_t[NV * NB];        // channel llrs, transposed
__device__ float g_ssign[NC * NB];        // 1 - 2*syndrome, transposed

// ---------------------------------------------------------------------------
__global__ void zero_cnt_kernel() {
    int tid = blockIdx.x * blockDim.x + threadIdx.x;
    if (tid < NC) g_csr_cnt[tid] = 0;
    if (tid < NV) g_csc_cnt[tid] = 0;
    if (tid < NB) {
        g_vbel[NV * NB + tid] = 0.0f;   // dummy var row
        g_cmsg[NC * NB + tid] = 0.0f;   // dummy check row
    }
}

// One warp per H row. Each lane keeps 4 independent uint4 loads in flight
// (MLP-4: proven sweet spot).
__global__ void extract_kernel(const uint4* __restrict__ H) {
    int warp = (blockIdx.x * blockDim.x + threadIdx.x) >> 5;
    if (warp >= NC) return;
    int lane = threadIdx.x & 31;
    const uint4* row = H + (size_t)warp * (NV / 4);   // 4096 uint4 per row

    for (int base = lane; base < NV / 4; base += 128) {
        uint4 u0 = row[base];
        uint4 u1 = row[base + 32];
        uint4 u2 = row[base + 64];
        uint4 u3 = row[base + 96];
        #pragma unroll
        for (int g = 0; g < 4; g++) {
            uint4 u = (g == 0) ? u0 : (g == 1) ? u1 : (g == 2) ? u2 : u3;
            if (u.x | u.y | u.z | u.w) {
                int vb = (base + g * 32) * 4;
                #pragma unroll
                for (int j = 0; j < 4; j++) {
                    unsigned val = (j == 0) ? u.x : (j == 1) ? u.y : (j == 2) ? u.z : u.w;
                    if (val) {
                        int v = vb + j;
                        int p = atomicAdd(&g_csr_cnt[warp], 1);
                        if (p < RCAP) g_csr_col[warp * RCAP + p] = v * NB;   // pre-scaled
                        int q = atomicAdd(&g_csc_cnt[v], 1);
                        if (q < CCAP) g_csc_row[v * CCAP + q] = warp * NB;   // pre-scaled
                    }
                }
            }
        }
    }
}

// Merged pad + prep (R10 structure, serial launch — extract has no spare
// bandwidth for overlap, proven R13).
#define PADB 64
__global__ void padprep_kernel(const float* __restrict__ syndrome,
                               const float* __restrict__ llr) {
    __shared__ float tile[32][33];
    int bid = blockIdx.x;
    if (bid < PADB) {
        int tid = bid * 256 + threadIdx.x;
        if (tid < NC) {
            int cnt = g_csr_cnt[tid]; if (cnt > RCAP) cnt = RCAP;
            int p = (cnt + 15) & ~15; if (p > RCAP) p = RCAP;
            if (p == 0) p = 16;
            for (int k = cnt; k < p; k++) g_csr_col[tid * RCAP + k] = NV * NB;
            g_csr_cnt[tid] = p;
        }
        if (tid < NV) {
            int cnt = g_csc_cnt[tid]; if (cnt > CCAP) cnt = CCAP;
            int p = (cnt + 7) & ~7;   if (p > CCAP) p = CCAP;
            if (p == 0) p = 8;
            for (int k = cnt; k < p; k++) g_csc_row[tid * CCAP + k] = NC * NB;
            g_csc_cnt[tid] = p;
        }
        return;
    }
    int tx = threadIdx.x & 31, ty = threadIdx.x >> 5;   // ty in 0..7
    int t = bid - PADB;
    if (t < NV / 32) {
        int v0 = t * 32;
        #pragma unroll
        for (int i = 0; i < 32; i += 8)
            tile[ty + i][tx] = llr[(size_t)(ty + i) * NV + v0 + tx];
        __syncthreads();
        #pragma unroll
        for (int i = 0; i < 32; i += 8) {
            float x = tile[tx][ty + i];
            int idx = (v0 + ty + i) * NB + tx;
            g_llr_t[idx] = x;
            g_vbel[idx]  = x;
        }
    } else {
        int c0 = (t - NV / 32) * 32;
        #pragma unroll
        for (int i = 0; i < 32; i += 8)
            tile[ty + i][tx] = syndrome[(size_t)(ty + i) * NC + c0 + tx];
        __syncthreads();
        #pragma unroll
        for (int i = 0; i < 32; i += 8)
            g_ssign[(c0 + ty + i) * NB + tx] = 1.0f - 2.0f * tile[tx][ty + i];
    }
}

__device__ __forceinline__ float fast_tanh(float x) {
    float y;
    asm("tanh.approx.f32 %0, %1;" : "=f"(y) : "f"(x));
    return y;
}

// Straight-line gather+sum over N4*4 indices read from (smem) index packs.
template <int N4>
__device__ __forceinline__ float gather_sum(const int4* p,
                                            const float* __restrict__ tbl,
                                            int lane) {
    int4 q[N4];
    #pragma unroll
    for (int i = 0; i < N4; i++) q[i] = p[i];
    float x[N4 * 4];
    #pragma unroll
    for (int i = 0; i < N4; i++) {
        x[4 * i + 0] = tbl[q[i].x + lane];
        x[4 * i + 1] = tbl[q[i].y + lane];
        x[4 * i + 2] = tbl[q[i].z + lane];
        x[4 * i + 3] = tbl[q[i].w + lane];
    }
    float s = 0.0f;
    #pragma unroll
    for (int i = 0; i < N4 * 4; i++) s += x[i];
    return s;
}

__device__ __forceinline__ float var_sum(int degp, const int4* rows, int lane) {
    if (degp == 8)       return gather_sum<2>(rows, g_cmsg, lane);
    else if (degp == 16) return gather_sum<4>(rows, g_cmsg, lane);
    float sum = 0.0f;                               // rare tail (24+)
    for (int k = 0; k < degp; k += 8)
        sum += gather_sum<2>(rows + (k >> 2), g_cmsg, lane);
    return sum;
}

// ---------------------------------------------------------------------------
// v -> c : ONE check per warp. PDL prelude stages the (static) index list
// into warp-private SMEM — L2 latency hidden in the overlap window; after
// gridsync index reads are LDS, leaving ONE exposed L2 round trip (gathers).
__global__ void __launch_bounds__(256, 8)
check_kernel(const float* __restrict__ w_vc) {
    cudaTriggerProgrammaticLaunchCompletion();
    __shared__ int s_cols[8][RCAP];                // 2 KB/CTA
    int wid = threadIdx.x >> 5;
    int lane = threadIdx.x & 31;
    int c = (blockIdx.x * blockDim.x + threadIdx.x) >> 5;
    bool active = (c < NC);

    int degp = 0;
    if (active) {
        degp = g_csr_cnt[c];                       // 16/32/48/64
        const int* cols = &g_csr_col[c * RCAP];
        s_cols[wid][lane]      = cols[lane];       // always in-bounds array
        s_cols[wid][lane + 32] = cols[lane + 32];  // garbage beyond degp OK
    }

    cudaGridDependencySynchronize();               // wait: predecessor's data
    if (!active) return;

    const int4* sc = (const int4*)s_cols[wid];
    float sum;
    if (degp == 16)      sum = gather_sum<4>(sc, g_vbel, lane);
    else if (degp == 32) sum = gather_sum<8>(sc, g_vbel, lane);
    else {                                          // rare tail (48/64)
        sum = 0.0f;
        for (int k = 0; k < degp; k += 16)
            sum += gather_sum<4>(sc + (k >> 2), g_vbel, lane);
    }

    float tt = fast_tanh(0.5f * (*w_vc) * sum);
    g_cmsg[c * NB + lane] = g_ssign[c * NB + lane] * tt;
}

// c -> v + damped update : TWO vars per warp (single full wave). The two
// vars' CSC rows are contiguous (80 ints) — staged to SMEM in the prelude.
__global__ void __launch_bounds__(256, 8)
var_kernel(const float* __restrict__ w_cv,
           const float* __restrict__ damping) {
    cudaTriggerProgrammaticLaunchCompletion();
    __shared__ int s_rows[8][2 * CCAP];            // 2.5 KB/CTA
    int wid = threadIdx.x >> 5;
    int lane = threadIdx.x & 31;
    int gw = (blockIdx.x * blockDim.x + threadIdx.x) >> 5;
    int v0 = gw * 2;
    bool active = (v0 < NV);

    int deg0 = 0, deg1 = 0;
    if (active) {
        deg0 = g_csc_cnt[v0];
        deg1 = g_csc_cnt[v0 + 1];
        const int* src = &g_csc_row[v0 * CCAP];    // 80 contiguous ints
        s_rows[wid][lane]      = src[lane];
        s_rows[wid][lane + 32] = src[lane + 32];
        if (lane < 16) s_rows[wid][lane + 64] = src[lane + 64];
    }

    cudaGridDependencySynchronize();               // wait: check phase done
    if (!active) return;

    const int4* p0 = (const int4*)s_rows[wid];
    const int4* p1 = p0 + (CCAP / 4);

    float sum0 = var_sum(deg0, p0, lane);
    float sum1 = var_sum(deg1, p1, lane);

    float dmp = *damping;
    float wc  = *w_cv;
    int idx0 = v0 * NB + lane;
    int idx1 = idx0 + NB;
    float old0 = g_vbel[idx0];
    float old1 = g_vbel[idx1];
    g_vbel[idx0] = dmp * old0 + (1.0f - dmp) * (g_llr_t[idx0] + wc * sum0);
    g_vbel[idx1] = dmp * old1 + (1.0f - dmp) * (g_llr_t[idx1] + wc * sum1);
}

// out[b][v] = sigmoid(-belief); smem-tile transpose, coalesced both sides.
__global__ void output_kernel(float* __restrict__ out) {
    __shared__ float tile[32][33];
    cudaGridDependencySynchronize();
    int tx = threadIdx.x & 31, ty = threadIdx.x >> 5;
    int v0 = blockIdx.x * 32;
    #pragma unroll
    for (int i = 0; i < 32; i += 8)
        tile[ty + i][tx] = g_vbel[(v0 + ty + i) * NB + tx];
    __syncthreads();
    #pragma unroll
    for (int i = 0; i < 32; i += 8) {
        float x = tile[tx][ty + i];
        out[(size_t)(ty + i) * NV + v0 + tx] = 1.0f / (1.0f + expf(x));
    }
}

// ---------------------------------------------------------------------------
template <typename... Args>
static void launch_pdl(void (*kern)(Args...), int grid, int block, Args... args) {
    cudaLaunchConfig_t cfg = {};
    cfg.gridDim  = dim3(grid, 1, 1);
    cfg.blockDim = dim3(block, 1, 1);
    cfg.stream   = 0;
    cudaLaunchAttribute attr[1];
    attr[0].id = cudaLaunchAttributeProgrammaticStreamSerialization;
    attr[0].val.programmaticStreamSerializationAllowed = 1;
    cfg.attrs = attr;
    cfg.numAttrs = 1;
    cudaLaunchKernelEx(&cfg, kern, args...);
}

extern "C" void kernel_launch(void* const* d_in, const int* in_sizes, int n_in,
                              void* d_out, int out_size) {
    const float* syndrome = (const float*)d_in[0];   // (32, 8192)
    const uint4* parity   = (const uint4*)d_in[1];   // (8192, 16384) fp32 as bits
    const float* llr      = (const float*)d_in[2];   // (32, 16384)
    const float* w_vc     = (const float*)d_in[3];
    const float* w_cv     = (const float*)d_in[4];
    const float* damping  = (const float*)d_in[5];
    float* out = (float*)d_out;

    zero_cnt_kernel<<<(NV + 255) / 256, 256>>>();
    extract_kernel<<<(NC * 32 + 255) / 256, 256>>>(parity);
    padprep_kernel<<<PADB + NV / 32 + NC / 32, 256>>>(syndrome, llr);

    for (int it = 0; it < NITR; it++) {
        launch_pdl(check_kernel, (NC * 32 + 255) / 256, 256, w_vc);
        launch_pdl(var_kernel,   (NV * 16 + 255) / 256, 256, w_cv, damping);
    }

    launch_pdl(output_kernel, NV / 32, 256, out);
}